// round 4
// baseline (speedup 1.0000x reference)
#include <cuda_runtime.h>
#include <cuda_bf16.h>

#define NN 100000
#define NE 1600000
#define INC 64
#define HID 128
#define NCLS 10
#define NG 64

// ---------------- scratch (device globals; no allocation) ----------------
__device__ int   g_is64;
__device__ int   g_deg[NN];
__device__ float g_dinv[NN];
__device__ int   g_off[NN + 1];
__device__ int   g_cur[NN];
__device__ int   g_csr_src[NE];
__device__ float g_csr_w[NE];
__device__ __align__(16) float g_aggx[(size_t)NN * INC];   // A @ x
__device__ __align__(16) float g_h[(size_t)NN * HID];      // layer activations
__device__ __align__(16) float g_t[(size_t)NN * HID];      // pre-agg transform
__device__ float g_pool[NG * HID];
__device__ int   g_cnt[NG];

// index loader: handles int32 or int64 source data via g_is64 flag
__device__ __forceinline__ int load_idx(const void* p, long long i, int is64) {
    if (is64) return (int)((const long long*)p)[i];
    return ((const int*)p)[i];
}

// ---------------- dtype detection ----------------
// int64 data with values < 2^31 has all odd 32-bit words == 0 (little endian).
// int32 data has real node indices there (all-zero probability ~0).
__global__ void k_detect(const int* __restrict__ ei32) {
    int all0 = 1;
    for (int i = 1; i < 64; i += 2)
        if (ei32[i] != 0) all0 = 0;
    g_is64 = all0;
}

// ---------------- graph preprocessing ----------------
__global__ void k_init_deg() {
    int i = blockIdx.x * blockDim.x + threadIdx.x;
    if (i < NN) g_deg[i] = 1;  // self-loop
}

__global__ void k_hist(const void* __restrict__ ei) {
    int e = blockIdx.x * blockDim.x + threadIdx.x;
    int is64 = g_is64;
    if (e < NE) {
        int d = load_idx(ei, (long long)NE + e, is64);
        atomicAdd(&g_deg[d], 1);
    }
}

// one-block hierarchical scan of counts = deg-1 -> exclusive offsets
__global__ void k_scan() {
    __shared__ int sh[1024];
    int t = threadIdx.x;
    const int C = (NN + 1023) / 1024;  // 98
    int lo = t * C, hi = min(NN, lo + C);
    int s = 0;
    for (int i = lo; i < hi; i++) s += g_deg[i] - 1;
    sh[t] = s;
    __syncthreads();
    for (int off = 1; off < 1024; off <<= 1) {
        int v = (t >= off) ? sh[t - off] : 0;
        __syncthreads();
        sh[t] += v;
        __syncthreads();
    }
    int run = sh[t] - s;  // exclusive base
    for (int i = lo; i < hi; i++) {
        g_off[i] = run;
        run += g_deg[i] - 1;
    }
    if (t == 1023) g_off[NN] = sh[1023];
}

__global__ void k_dinv() {
    int i = blockIdx.x * blockDim.x + threadIdx.x;
    if (i < NN) {
        g_dinv[i] = rsqrtf((float)g_deg[i]);
        g_cur[i] = g_off[i];
    }
}

__global__ void k_build(const void* __restrict__ ei) {
    int e = blockIdx.x * blockDim.x + threadIdx.x;
    int is64 = g_is64;
    if (e < NE) {
        int s = load_idx(ei, e, is64);
        int d = load_idx(ei, (long long)NE + e, is64);
        int pos = atomicAdd(&g_cur[d], 1);
        g_csr_src[pos] = s;
        g_csr_w[pos] = g_dinv[s] * g_dinv[d];
    }
}

// ---------------- aggregation ----------------
// warp per node, 64 cols (float2 per lane): g_aggx = A @ x
__global__ void k_agg1(const float* __restrict__ x) {
    int warp = (blockIdx.x * blockDim.x + threadIdx.x) >> 5;
    if (warp >= NN) return;
    int lane = threadIdx.x & 31;
    const float2* x2 = (const float2*)x;
    float di = g_dinv[warp];
    float2 v = x2[(size_t)warp * 32 + lane];
    float sw = di * di;
    float2 acc = make_float2(sw * v.x, sw * v.y);
    int beg = g_off[warp], end = g_off[warp + 1];
    for (int base = beg; base < end; base += 32) {
        int p = base + lane;
        int sj = 0; float wj = 0.f;
        if (p < end) { sj = g_csr_src[p]; wj = g_csr_w[p]; }
        int c = min(32, end - base);
        for (int t = 0; t < c; t++) {
            int s = __shfl_sync(0xffffffffu, sj, t);
            float w = __shfl_sync(0xffffffffu, wj, t);
            float2 u = x2[(size_t)s * 32 + lane];
            acc.x += w * u.x;
            acc.y += w * u.y;
        }
    }
    ((float2*)g_aggx)[(size_t)warp * 32 + lane] = acc;
}

// warp per node, 128 cols (float4 per lane): g_h = relu(A @ g_t + b2)
__global__ void k_agg2(const float* __restrict__ b2) {
    int warp = (blockIdx.x * blockDim.x + threadIdx.x) >> 5;
    if (warp >= NN) return;
    int lane = threadIdx.x & 31;
    const float4* t4 = (const float4*)g_t;
    float di = g_dinv[warp];
    float4 v = t4[(size_t)warp * 32 + lane];
    float sw = di * di;
    float4 acc = make_float4(sw * v.x, sw * v.y, sw * v.z, sw * v.w);
    int beg = g_off[warp], end = g_off[warp + 1];
    for (int base = beg; base < end; base += 32) {
        int p = base + lane;
        int sj = 0; float wj = 0.f;
        if (p < end) { sj = g_csr_src[p]; wj = g_csr_w[p]; }
        int c = min(32, end - base);
        for (int t = 0; t < c; t++) {
            int s = __shfl_sync(0xffffffffu, sj, t);
            float w = __shfl_sync(0xffffffffu, wj, t);
            float4 u = t4[(size_t)s * 32 + lane];
            acc.x += w * u.x;
            acc.y += w * u.y;
            acc.z += w * u.z;
            acc.w += w * u.w;
        }
    }
    float4 b = ((const float4*)b2)[lane];
    acc.x = fmaxf(acc.x + b.x, 0.f);
    acc.y = fmaxf(acc.y + b.y, 0.f);
    acc.z = fmaxf(acc.z + b.z, 0.f);
    acc.w = fmaxf(acc.w + b.w, 0.f);
    ((float4*)g_h)[(size_t)warp * 32 + lane] = acc;
}

// ---------------- GEMM (K-slice of 64, N=128 out cols) ----------------
__global__ void __launch_bounds__(128) k_gemm64(
    const float* __restrict__ in, int istride,
    const float* __restrict__ W64, const float* __restrict__ bias,
    float* __restrict__ out, int n, int accumulate, int dorelu)
{
    __shared__ float sW[64 * 128];
    __shared__ float sX[16 * 64];
    int j = threadIdx.x;
    for (int i = j; i < 64 * 128; i += 128) sW[i] = W64[i];
    __syncthreads();
    int ntiles = (n + 15) / 16;
    for (int tile = blockIdx.x; tile < ntiles; tile += gridDim.x) {
        int row0 = tile * 16;
        int rows = min(16, n - row0);
        for (int i = j; i < rows * 64; i += 128) {
            int r = i >> 6, k = i & 63;
            sX[i] = in[(size_t)(row0 + r) * istride + k];
        }
        __syncthreads();
        float acc[16];
#pragma unroll
        for (int r = 0; r < 16; r++) acc[r] = 0.f;
#pragma unroll 4
        for (int k = 0; k < 64; k++) {
            float w = sW[k * 128 + j];
#pragma unroll
            for (int r = 0; r < 16; r++) acc[r] += sX[r * 64 + k] * w;
        }
        float b = bias ? bias[j] : 0.f;
        for (int r = 0; r < rows; r++) {
            float v = acc[r] + b;
            if (accumulate) v += out[(size_t)(row0 + r) * 128 + j];
            if (dorelu) v = fmaxf(v, 0.f);
            out[(size_t)(row0 + r) * 128 + j] = v;
        }
        __syncthreads();
    }
}

// ---------------- pooling + classifier ----------------
__global__ void k_pool_init() {
    int i = blockIdx.x * blockDim.x + threadIdx.x;
    if (i < NG * HID) g_pool[i] = 0.f;
    if (i < NG) g_cnt[i] = 0;
}

#define POOL_BLOCKS 64
__global__ void __launch_bounds__(128) k_pool_acc(const void* __restrict__ batch) {
    __shared__ float sacc[NG * HID];  // 32 KB
    __shared__ int scnt[NG];
    int t = threadIdx.x;
    int is64 = g_is64;
    for (int i = t; i < NG * HID; i += 128) sacc[i] = 0.f;
    if (t < NG) scnt[t] = 0;
    __syncthreads();
    int chunk = (NN + POOL_BLOCKS - 1) / POOL_BLOCKS;
    int lo = blockIdx.x * chunk, hi = min(NN, lo + chunk);
    float acc = 0.f;
    int cg = -1;
    for (int nd = lo; nd < hi; nd++) {
        int g = load_idx(batch, nd, is64);
        if (g != cg) {
            if (cg >= 0) sacc[cg * HID + t] += acc;
            acc = 0.f;
            cg = g;
        }
        acc += g_h[(size_t)nd * HID + t];
        if (t == 0) scnt[g]++;
    }
    if (cg >= 0) sacc[cg * HID + t] += acc;
    __syncthreads();
    for (int i = t; i < NG * HID; i += 128)
        if (sacc[i] != 0.f) atomicAdd(&g_pool[i], sacc[i]);
    if (t < NG && scnt[t]) atomicAdd(&g_cnt[t], scnt[t]);
}

__global__ void k_final(const float* __restrict__ Wc, const float* __restrict__ bc,
                        float* __restrict__ out) {
    int tid = threadIdx.x;  // 640 threads
    int g = tid / NCLS, c = tid % NCLS;
    float s = 0.f;
#pragma unroll 8
    for (int h = 0; h < HID; h++) s += g_pool[g * HID + h] * Wc[h * NCLS + c];
    float cnt = (float)max(g_cnt[g], 1);
    out[tid] = s / cnt + bc[c];
}

// ---------------- launch ----------------
extern "C" void kernel_launch(void* const* d_in, const int* in_sizes, int n_in,
                              void* d_out, int out_size) {
    const float* x  = (const float*)d_in[0];
    const float* W1 = (const float*)d_in[1];
    const float* b1 = (const float*)d_in[2];
    const float* W2 = (const float*)d_in[3];
    const float* b2 = (const float*)d_in[4];
    const float* Wc = (const float*)d_in[5];
    const float* bc = (const float*)d_in[6];
    const void* ei    = d_in[7];
    const void* batch = d_in[8];
    float* out = (float*)d_out;

    // Resolve REAL device addresses of __device__ globals (host symbol refs
    // are host-shadow addresses — silently wrong on ATS-capable GB300).
    static float* p_aggx = nullptr;
    static float* p_h = nullptr;
    static float* p_t = nullptr;
    if (!p_aggx) {
        cudaGetSymbolAddress((void**)&p_aggx, g_aggx);
        cudaGetSymbolAddress((void**)&p_h, g_h);
        cudaGetSymbolAddress((void**)&p_t, g_t);
    }

    // dtype detection + graph structure
    k_detect<<<1, 1>>>((const int*)ei);
    k_init_deg<<<(NN + 255) / 256, 256>>>();
    k_hist<<<(NE + 511) / 512, 512>>>(ei);
    k_scan<<<1, 1024>>>();
    k_dinv<<<(NN + 255) / 256, 256>>>();
    k_build<<<(NE + 511) / 512, 512>>>(ei);

    // layer 1: aggregate-then-transform   h = relu((A x) W1 + b1)
    k_agg1<<<(NN * 32 + 255) / 256, 256>>>(x);
    k_gemm64<<<640, 128>>>(p_aggx, INC, W1, b1, p_h, NN, 0, 1);

    // layer 2: transform-then-aggregate   h = relu(A (h W2) + b2)
    k_gemm64<<<640, 128>>>(p_h, HID, W2, nullptr, p_t, NN, 0, 0);
    k_gemm64<<<640, 128>>>(p_h + 64, HID, W2 + 64 * 128, nullptr, p_t, NN, 1, 0);
    k_agg2<<<(NN * 32 + 255) / 256, 256>>>(b2);

    // mean pool + classifier
    k_pool_init<<<(NG * HID + 255) / 256, 256>>>();
    k_pool_acc<<<POOL_BLOCKS, 128>>>(batch);
    k_final<<<1, NG * NCLS>>>(Wc, bc, out);
}

// round 9
// speedup vs baseline: 1.1476x; 1.1476x over previous
#include <cuda_runtime.h>
#include <cuda_bf16.h>

#define NN 100000
#define NE 1600000
#define INC 64
#define HID 128
#define NCLS 10
#define NG 64
#define SCAN_BLK ((NN + 1023) / 1024)   // 98

// ---------------- scratch (device globals; no allocation) ----------------
__device__ int   g_is64;
__device__ int   g_deg[NN];
__device__ float g_dinv[NN];
__device__ int   g_off[NN + 1];
__device__ int   g_cur[NN];
__device__ int2  g_csr[NE];            // (src, weight bits) interleaved
__device__ int   g_part[128];
__device__ int   g_pbase[128];
__device__ __align__(16) float g_aggx[(size_t)NN * INC];   // A @ x
__device__ __align__(16) float g_h[(size_t)NN * HID];      // layer activations
__device__ __align__(16) float g_t[(size_t)NN * HID];      // pre-agg transform
__device__ float g_pool[NG * HID];
__device__ int   g_cnt[NG];

// index loader: handles int32 or int64 source data via g_is64 flag
__device__ __forceinline__ int load_idx(const void* p, long long i, int is64) {
    if (is64) return (int)((const long long*)p)[i];
    return ((const int*)p)[i];
}

// ---------------- dtype detection ----------------
__global__ void k_detect(const int* __restrict__ ei32) {
    int all0 = 1;
    for (int i = 1; i < 64; i += 2)
        if (ei32[i] != 0) all0 = 0;
    g_is64 = all0;
}

// ---------------- graph preprocessing ----------------
__global__ void k_init_deg() {
    int i = blockIdx.x * blockDim.x + threadIdx.x;
    if (i < NN) g_deg[i] = 1;  // self-loop
}

__global__ void k_hist(const void* __restrict__ ei) {
    int e = blockIdx.x * blockDim.x + threadIdx.x;
    int is64 = g_is64;
    if (e < NE) {
        int d = load_idx(ei, (long long)NE + e, is64);
        atomicAdd(&g_deg[d], 1);
    }
}

// ---- hierarchical scan of (deg-1) -> exclusive offsets ----
__global__ void __launch_bounds__(256) k_scan_a() {
    __shared__ int sh[256];
    int t = threadIdx.x, b = blockIdx.x;
    int base = b * 1024 + t * 4;
    int v[4];
#pragma unroll
    for (int i = 0; i < 4; i++)
        v[i] = (base + i < NN) ? (g_deg[base + i] - 1) : 0;
    int ts = v[0] + v[1] + v[2] + v[3];
    sh[t] = ts;
    __syncthreads();
    int acc = ts;
#pragma unroll
    for (int off = 1; off < 256; off <<= 1) {
        int u = (t >= off) ? sh[t - off] : 0;
        __syncthreads();
        acc += u;
        sh[t] = acc;
        __syncthreads();
    }
    int run = acc - ts;  // exclusive base for this thread
#pragma unroll
    for (int i = 0; i < 4; i++) {
        if (base + i < NN) g_off[base + i] = run;
        run += v[i];
    }
    if (t == 255) g_part[b] = acc;  // block total
}

__global__ void k_scan_b() {
    __shared__ int sh[128];
    int t = threadIdx.x;
    int v = (t < SCAN_BLK) ? g_part[t] : 0;
    sh[t] = v;
    __syncthreads();
    int acc = v;
#pragma unroll
    for (int off = 1; off < 128; off <<= 1) {
        int u = (t >= off) ? sh[t - off] : 0;
        __syncthreads();
        acc += u;
        sh[t] = acc;
        __syncthreads();
    }
    if (t < SCAN_BLK) g_pbase[t] = acc - v;
    if (t == 127) g_off[NN] = acc;  // grand total
}

__global__ void k_scan_c() {
    int i = blockIdx.x * blockDim.x + threadIdx.x;
    if (i < NN) {
        int o = g_off[i] + g_pbase[i >> 10];
        g_off[i] = o;
        g_cur[i] = o;
        g_dinv[i] = rsqrtf((float)g_deg[i]);
    }
}

__global__ void k_build(const void* __restrict__ ei) {
    int e = blockIdx.x * blockDim.x + threadIdx.x;
    int is64 = g_is64;
    if (e < NE) {
        int s = load_idx(ei, e, is64);
        int d = load_idx(ei, (long long)NE + e, is64);
        int pos = atomicAdd(&g_cur[d], 1);
        float w = g_dinv[s] * g_dinv[d];
        g_csr[pos] = make_int2(s, __float_as_int(w));
    }
}

// ---------------- aggregation ----------------
// warp per node, 64 cols (float2 per lane): g_aggx = A @ x
__global__ void k_agg1(const float* __restrict__ x) {
    int warp = (blockIdx.x * blockDim.x + threadIdx.x) >> 5;
    if (warp >= NN) return;
    int lane = threadIdx.x & 31;
    const float2* x2 = (const float2*)x;
    float di = g_dinv[warp];
    float2 v = x2[(size_t)warp * 32 + lane];
    float sw = di * di;
    float2 acc = make_float2(sw * v.x, sw * v.y);
    int beg = g_off[warp], end = g_off[warp + 1];
#pragma unroll 4
    for (int p = beg; p < end; p++) {
        int2 e = __ldg(&g_csr[p]);       // same addr all lanes -> broadcast
        float w = __int_as_float(e.y);
        float2 u = __ldg(&x2[(size_t)e.x * 32 + lane]);
        acc.x += w * u.x;
        acc.y += w * u.y;
    }
    ((float2*)g_aggx)[(size_t)warp * 32 + lane] = acc;
}

// warp per node, 128 cols (float4 per lane): g_h = relu(A @ g_t + b2)
__global__ void k_agg2(const float* __restrict__ b2) {
    int warp = (blockIdx.x * blockDim.x + threadIdx.x) >> 5;
    if (warp >= NN) return;
    int lane = threadIdx.x & 31;
    const float4* t4 = (const float4*)g_t;
    float di = g_dinv[warp];
    float4 v = t4[(size_t)warp * 32 + lane];
    float sw = di * di;
    float4 acc = make_float4(sw * v.x, sw * v.y, sw * v.z, sw * v.w);
    int beg = g_off[warp], end = g_off[warp + 1];
#pragma unroll 4
    for (int p = beg; p < end; p++) {
        int2 e = __ldg(&g_csr[p]);
        float w = __int_as_float(e.y);
        float4 u = __ldg(&t4[(size_t)e.x * 32 + lane]);
        acc.x += w * u.x;
        acc.y += w * u.y;
        acc.z += w * u.z;
        acc.w += w * u.w;
    }
    float4 b = ((const float4*)b2)[lane];
    acc.x = fmaxf(acc.x + b.x, 0.f);
    acc.y = fmaxf(acc.y + b.y, 0.f);
    acc.z = fmaxf(acc.z + b.z, 0.f);
    acc.w = fmaxf(acc.w + b.w, 0.f);
    ((float4*)g_h)[(size_t)warp * 32 + lane] = acc;
}

// ---------------- GEMM layer 1 (K=64, N=128 out cols) ----------------
__global__ void __launch_bounds__(128) k_gemm64(
    const float* __restrict__ in,
    const float* __restrict__ W64, const float* __restrict__ bias,
    float* __restrict__ out, int n)
{
    __shared__ float sW[64 * 128];
    __shared__ float sX[16 * 64];
    int j = threadIdx.x;
    for (int i = j; i < 64 * 128; i += 128) sW[i] = W64[i];
    __syncthreads();
    int ntiles = (n + 15) / 16;
    for (int tile = blockIdx.x; tile < ntiles; tile += gridDim.x) {
        int row0 = tile * 16;
        int rows = min(16, n - row0);
        for (int i = j; i < rows * 64; i += 128) {
            int r = i >> 6, k = i & 63;
            sX[i] = in[(size_t)(row0 + r) * 64 + k];
        }
        __syncthreads();
        float acc[16];
#pragma unroll
        for (int r = 0; r < 16; r++) acc[r] = 0.f;
#pragma unroll 4
        for (int k = 0; k < 64; k++) {
            float w = sW[k * 128 + j];
#pragma unroll
            for (int r = 0; r < 16; r++) acc[r] += sX[r * 64 + k] * w;
        }
        float b = bias[j];
        for (int r = 0; r < rows; r++)
            out[(size_t)(row0 + r) * 128 + j] = fmaxf(acc[r] + b, 0.f);
        __syncthreads();
    }
}

// ---------------- GEMM layer 2 (K=128, N=128, full W persistent) ----------
// dynamic smem: sW 128*128 floats (64KB) + sX 16*128 floats (8KB)
__global__ void __launch_bounds__(128) k_gemm128(
    const float* __restrict__ in, const float* __restrict__ W,
    float* __restrict__ out, int n)
{
    extern __shared__ float dyn[];
    float* sW = dyn;               // 128*128
    float* sX = dyn + 128 * 128;   // 16*128
    int j = threadIdx.x;
    for (int i = j; i < 128 * 128; i += 128) sW[i] = W[i];
    __syncthreads();
    int ntiles = (n + 15) / 16;
    for (int tile = blockIdx.x; tile < ntiles; tile += gridDim.x) {
        int row0 = tile * 16;
        int rows = min(16, n - row0);
        for (int i = j; i < rows * 128; i += 128) {
            int r = i >> 7, k = i & 127;
            sX[i] = in[(size_t)(row0 + r) * 128 + k];
        }
        __syncthreads();
        float acc[16];
#pragma unroll
        for (int r = 0; r < 16; r++) acc[r] = 0.f;
#pragma unroll 4
        for (int k = 0; k < 128; k++) {
            float w = sW[k * 128 + j];
#pragma unroll
            for (int r = 0; r < 16; r++) acc[r] += sX[r * 128 + k] * w;
        }
        for (int r = 0; r < rows; r++)
            out[(size_t)(row0 + r) * 128 + j] = acc[r];
        __syncthreads();
    }
}

// ---------------- pooling + classifier ----------------
__global__ void k_pool_init() {
    int i = blockIdx.x * blockDim.x + threadIdx.x;
    if (i < NG * HID) g_pool[i] = 0.f;
    if (i < NG) g_cnt[i] = 0;
}

#define POOL_BLOCKS 64
__global__ void __launch_bounds__(128) k_pool_acc(const void* __restrict__ batch) {
    __shared__ float sacc[NG * HID];  // 32 KB
    __shared__ int scnt[NG];
    int t = threadIdx.x;
    int is64 = g_is64;
    for (int i = t; i < NG * HID; i += 128) sacc[i] = 0.f;
    if (t < NG) scnt[t] = 0;
    __syncthreads();
    int chunk = (NN + POOL_BLOCKS - 1) / POOL_BLOCKS;
    int lo = blockIdx.x * chunk, hi = min(NN, lo + chunk);
    float acc = 0.f;
    int cg = -1;
    for (int nd = lo; nd < hi; nd++) {
        int g = load_idx(batch, nd, is64);
        if (g != cg) {
            if (cg >= 0) sacc[cg * HID + t] += acc;
            acc = 0.f;
            cg = g;
        }
        acc += g_h[(size_t)nd * HID + t];
        if (t == 0) scnt[g]++;
    }
    if (cg >= 0) sacc[cg * HID + t] += acc;
    __syncthreads();
    for (int i = t; i < NG * HID; i += 128)
        if (sacc[i] != 0.f) atomicAdd(&g_pool[i], sacc[i]);
    if (t < NG && scnt[t]) atomicAdd(&g_cnt[t], scnt[t]);
}

__global__ void k_final(const float* __restrict__ Wc, const float* __restrict__ bc,
                        float* __restrict__ out) {
    int tid = threadIdx.x;  // 640 threads
    int g = tid / NCLS, c = tid % NCLS;
    float s = 0.f;
#pragma unroll 8
    for (int h = 0; h < HID; h++) s += g_pool[g * HID + h] * Wc[h * NCLS + c];
    float cnt = (float)max(g_cnt[g], 1);
    out[tid] = s / cnt + bc[c];
}

// ---------------- launch ----------------
extern "C" void kernel_launch(void* const* d_in, const int* in_sizes, int n_in,
                              void* d_out, int out_size) {
    const float* x  = (const float*)d_in[0];
    const float* W1 = (const float*)d_in[1];
    const float* b1 = (const float*)d_in[2];
    const float* W2 = (const float*)d_in[3];
    const float* b2 = (const float*)d_in[4];
    const float* Wc = (const float*)d_in[5];
    const float* bc = (const float*)d_in[6];
    const void* ei    = d_in[7];
    const void* batch = d_in[8];
    float* out = (float*)d_out;

    const int GEMM128_SMEM = (128 * 128 + 16 * 128) * 4;  // 72 KB

    // Resolve REAL device addresses of __device__ globals (host symbol refs
    // are host-shadow addresses — silently wrong on ATS-capable GB300).
    static float* p_aggx = nullptr;
    static float* p_h = nullptr;
    static float* p_t = nullptr;
    if (!p_aggx) {
        cudaGetSymbolAddress((void**)&p_aggx, g_aggx);
        cudaGetSymbolAddress((void**)&p_h, g_h);
        cudaGetSymbolAddress((void**)&p_t, g_t);
        cudaFuncSetAttribute(k_gemm128,
                             cudaFuncAttributeMaxDynamicSharedMemorySize,
                             GEMM128_SMEM);
    }

    // dtype detection + graph structure
    k_detect<<<1, 1>>>((const int*)ei);
    k_init_deg<<<(NN + 255) / 256, 256>>>();
    k_hist<<<(NE + 511) / 512, 512>>>(ei);
    k_scan_a<<<SCAN_BLK, 256>>>();
    k_scan_b<<<1, 128>>>();
    k_scan_c<<<(NN + 255) / 256, 256>>>();
    k_build<<<(NE + 511) / 512, 512>>>(ei);

    // layer 1: aggregate-then-transform   h = relu((A x) W1 + b1)
    k_agg1<<<(NN * 32 + 255) / 256, 256>>>(x);
    k_gemm64<<<640, 128>>>(p_aggx, W1, b1, p_h, NN);

    // layer 2: transform-then-aggregate   h = relu(A (h W2) + b2)
    k_gemm128<<<640, 128, GEMM128_SMEM>>>(p_h, W2, p_t, NN);
    k_agg2<<<(NN * 32 + 255) / 256, 256>>>(b2);

    // mean pool + classifier
    k_pool_init<<<(NG * HID + 255) / 256, 256>>>();
    k_pool_acc<<<POOL_BLOCKS, 128>>>(batch);
    k_final<<<1, NG * NCLS>>>(Wc, bc, out);
}

// round 10
// speedup vs baseline: 2.0159x; 1.7567x over previous
#include <cuda_runtime.h>
#include <cuda_bf16.h>

#define NN 100000
#define NE 1600000
#define INC 64
#define HID 128
#define NCLS 10
#define NG 64
#define SCAN_BLK ((NN + 1023) / 1024)   // 98

// ---------------- scratch (device globals; no allocation) ----------------
__device__ int   g_is64;
__device__ int   g_deg[NN];
__device__ float g_dinv[NN];
__device__ int   g_off[NN + 1];
__device__ int   g_cur[NN];
__device__ int2  g_csr[NE];            // (src, weight bits) interleaved
__device__ int   g_part[128];
__device__ int   g_pbase[128];
__device__ __align__(16) float g_aggx[(size_t)NN * INC];   // A @ x
__device__ __align__(16) float g_h[(size_t)NN * HID];      // layer activations
__device__ __align__(16) float g_t[(size_t)NN * HID];      // pre-agg transform
__device__ float g_pool[NG * HID];
__device__ int   g_cnt[NG];

__device__ __forceinline__ int load_idx(const void* p, long long i, int is64) {
    if (is64) return (int)((const long long*)p)[i];
    return ((const int*)p)[i];
}

// ---------------- dtype detection ----------------
__global__ void k_detect(const int* __restrict__ ei32) {
    int all0 = 1;
    for (int i = 1; i < 64; i += 2)
        if (ei32[i] != 0) all0 = 0;
    g_is64 = all0;
}

// ---------------- graph preprocessing ----------------
__global__ void k_init_deg() {
    int i = blockIdx.x * blockDim.x + threadIdx.x;
    if (i < NN) g_deg[i] = 1;  // self-loop
}

__global__ void k_hist(const void* __restrict__ ei) {
    int e = blockIdx.x * blockDim.x + threadIdx.x;
    int is64 = g_is64;
    if (e < NE) {
        int d = load_idx(ei, (long long)NE + e, is64);
        atomicAdd(&g_deg[d], 1);
    }
}

// ---- hierarchical scan of (deg-1) -> exclusive offsets ----
__global__ void __launch_bounds__(256) k_scan_a() {
    __shared__ int sh[256];
    int t = threadIdx.x, b = blockIdx.x;
    int base = b * 1024 + t * 4;
    int v[4];
#pragma unroll
    for (int i = 0; i < 4; i++)
        v[i] = (base + i < NN) ? (g_deg[base + i] - 1) : 0;
    int ts = v[0] + v[1] + v[2] + v[3];
    sh[t] = ts;
    __syncthreads();
    int acc = ts;
#pragma unroll
    for (int off = 1; off < 256; off <<= 1) {
        int u = (t >= off) ? sh[t - off] : 0;
        __syncthreads();
        acc += u;
        sh[t] = acc;
        __syncthreads();
    }
    int run = acc - ts;
#pragma unroll
    for (int i = 0; i < 4; i++) {
        if (base + i < NN) g_off[base + i] = run;
        run += v[i];
    }
    if (t == 255) g_part[b] = acc;
}

__global__ void k_scan_b() {
    __shared__ int sh[128];
    int t = threadIdx.x;
    int v = (t < SCAN_BLK) ? g_part[t] : 0;
    sh[t] = v;
    __syncthreads();
    int acc = v;
#pragma unroll
    for (int off = 1; off < 128; off <<= 1) {
        int u = (t >= off) ? sh[t - off] : 0;
        __syncthreads();
        acc += u;
        sh[t] = acc;
        __syncthreads();
    }
    if (t < SCAN_BLK) g_pbase[t] = acc - v;
    if (t == 127) g_off[NN] = acc;
}

__global__ void k_scan_c() {
    int i = blockIdx.x * blockDim.x + threadIdx.x;
    if (i < NN) {
        int o = g_off[i] + g_pbase[i >> 10];
        g_off[i] = o;
        g_cur[i] = o;
        g_dinv[i] = rsqrtf((float)g_deg[i]);
    }
}

__global__ void k_build(const void* __restrict__ ei) {
    int e = blockIdx.x * blockDim.x + threadIdx.x;
    int is64 = g_is64;
    if (e < NE) {
        int s = load_idx(ei, e, is64);
        int d = load_idx(ei, (long long)NE + e, is64);
        int pos = atomicAdd(&g_cur[d], 1);
        float w = g_dinv[s] * g_dinv[d];
        g_csr[pos] = make_int2(s, __float_as_int(w));
    }
}

// ---------------- aggregation ----------------
// warp per node, 64 cols (float2 per lane): g_aggx = A @ x
__global__ void k_agg1(const float* __restrict__ x) {
    int warp = (blockIdx.x * blockDim.x + threadIdx.x) >> 5;
    if (warp >= NN) return;
    int lane = threadIdx.x & 31;
    const float2* x2 = (const float2*)x;
    float di = g_dinv[warp];
    float2 v = x2[(size_t)warp * 32 + lane];
    float sw = di * di;
    float2 acc = make_float2(sw * v.x, sw * v.y);
    int beg = g_off[warp], end = g_off[warp + 1];
#pragma unroll 8
    for (int p = beg; p < end; p++) {
        int2 e = __ldg(&g_csr[p]);       // same addr all lanes -> broadcast
        float w = __int_as_float(e.y);
        float2 u = __ldg(&x2[(size_t)e.x * 32 + lane]);
        acc.x += w * u.x;
        acc.y += w * u.y;
    }
    ((float2*)g_aggx)[(size_t)warp * 32 + lane] = acc;
}

// warp per node, 128 cols (float4 per lane): g_h = relu(A @ g_t + b2)
__global__ void k_agg2(const float* __restrict__ b2) {
    int warp = (blockIdx.x * blockDim.x + threadIdx.x) >> 5;
    if (warp >= NN) return;
    int lane = threadIdx.x & 31;
    const float4* t4 = (const float4*)g_t;
    float di = g_dinv[warp];
    float4 v = t4[(size_t)warp * 32 + lane];
    float sw = di * di;
    float4 acc = make_float4(sw * v.x, sw * v.y, sw * v.z, sw * v.w);
    int beg = g_off[warp], end = g_off[warp + 1];
#pragma unroll 8
    for (int p = beg; p < end; p++) {
        int2 e = __ldg(&g_csr[p]);
        float w = __int_as_float(e.y);
        float4 u = __ldg(&t4[(size_t)e.x * 32 + lane]);
        acc.x += w * u.x;
        acc.y += w * u.y;
        acc.z += w * u.z;
        acc.w += w * u.w;
    }
    float4 b = ((const float4*)b2)[lane];
    acc.x = fmaxf(acc.x + b.x, 0.f);
    acc.y = fmaxf(acc.y + b.y, 0.f);
    acc.z = fmaxf(acc.z + b.z, 0.f);
    acc.w = fmaxf(acc.w + b.w, 0.f);
    ((float4*)g_h)[(size_t)warp * 32 + lane] = acc;
}

// ---------------- GEMM layer 1 (K=64, N=128 out cols) ----------------
__global__ void __launch_bounds__(128) k_gemm64(
    const float* __restrict__ in,
    const float* __restrict__ W64, const float* __restrict__ bias,
    float* __restrict__ out, int n)
{
    __shared__ float sW[64 * 128];
    __shared__ __align__(16) float sX[16 * 64];
    int j = threadIdx.x;
    for (int i = j; i < 64 * 128; i += 128) sW[i] = W64[i];
    __syncthreads();
    int ntiles = (n + 15) / 16;
    for (int tile = blockIdx.x; tile < ntiles; tile += gridDim.x) {
        int row0 = tile * 16;
        int rows = min(16, n - row0);
        for (int i = j; i < rows * 64; i += 128) {
            int r = i >> 6, k = i & 63;
            sX[i] = in[(size_t)(row0 + r) * 64 + k];
        }
        __syncthreads();
        float acc[16];
#pragma unroll
        for (int r = 0; r < 16; r++) acc[r] = 0.f;
#pragma unroll 2
        for (int k4 = 0; k4 < 64; k4 += 4) {
            float w0 = sW[(k4 + 0) * 128 + j];
            float w1 = sW[(k4 + 1) * 128 + j];
            float w2 = sW[(k4 + 2) * 128 + j];
            float w3 = sW[(k4 + 3) * 128 + j];
#pragma unroll
            for (int r = 0; r < 16; r++) {
                float4 xv = *(const float4*)&sX[r * 64 + k4];
                acc[r] += xv.x * w0 + xv.y * w1 + xv.z * w2 + xv.w * w3;
            }
        }
        float b = bias[j];
        for (int r = 0; r < rows; r++)
            out[(size_t)(row0 + r) * 128 + j] = fmaxf(acc[r] + b, 0.f);
        __syncthreads();
    }
}

// ---------------- GEMM layer 2 (K=128, N=128, full W persistent) ----------
__global__ void __launch_bounds__(128) k_gemm128(
    const float* __restrict__ in, const float* __restrict__ W,
    float* __restrict__ out, int n)
{
    extern __shared__ __align__(16) float dyn[];
    float* sW = dyn;               // 128*128
    float* sX = dyn + 128 * 128;   // 16*128
    int j = threadIdx.x;
    for (int i = j; i < 128 * 128; i += 128) sW[i] = W[i];
    __syncthreads();
    int ntiles = (n + 15) / 16;
    for (int tile = blockIdx.x; tile < ntiles; tile += gridDim.x) {
        int row0 = tile * 16;
        int rows = min(16, n - row0);
        for (int i = j; i < rows * 128; i += 128) {
            int r = i >> 7, k = i & 127;
            sX[i] = in[(size_t)(row0 + r) * 128 + k];
        }
        __syncthreads();
        float acc[16];
#pragma unroll
        for (int r = 0; r < 16; r++) acc[r] = 0.f;
#pragma unroll 2
        for (int k4 = 0; k4 < 128; k4 += 4) {
            float w0 = sW[(k4 + 0) * 128 + j];
            float w1 = sW[(k4 + 1) * 128 + j];
            float w2 = sW[(k4 + 2) * 128 + j];
            float w3 = sW[(k4 + 3) * 128 + j];
#pragma unroll
            for (int r = 0; r < 16; r++) {
                float4 xv = *(const float4*)&sX[r * 128 + k4];
                acc[r] += xv.x * w0 + xv.y * w1 + xv.z * w2 + xv.w * w3;
            }
        }
        for (int r = 0; r < rows; r++)
            out[(size_t)(row0 + r) * 128 + j] = acc[r];
        __syncthreads();
    }
}

// ---------------- pooling + classifier ----------------
__global__ void k_pool_init() {
    int i = blockIdx.x * blockDim.x + threadIdx.x;
    if (i < NG * HID) g_pool[i] = 0.f;
    if (i < NG) g_cnt[i] = 0;
}

#define POOL_BLOCKS 1024
__global__ void __launch_bounds__(128) k_pool_acc(const void* __restrict__ batch) {
    int t = threadIdx.x;
    int is64 = g_is64;
    const int chunk = (NN + POOL_BLOCKS - 1) / POOL_BLOCKS;  // 98
    int lo = blockIdx.x * chunk, hi = min(NN, lo + chunk);
    if (lo >= hi) return;
    float acc = 0.f;
    int cg = -1, cnt = 0;
    for (int nd = lo; nd < hi; nd++) {
        int g = load_idx(batch, nd, is64);
        if (g != cg) {
            if (cg >= 0) {
                atomicAdd(&g_pool[cg * HID + t], acc);
                if (t == 0) atomicAdd(&g_cnt[cg], cnt);
            }
            acc = 0.f; cnt = 0; cg = g;
        }
        acc += g_h[(size_t)nd * HID + t];
        cnt++;
    }
    if (cg >= 0) {
        atomicAdd(&g_pool[cg * HID + t], acc);
        if (t == 0) atomicAdd(&g_cnt[cg], cnt);
    }
}

__global__ void k_final(const float* __restrict__ Wc, const float* __restrict__ bc,
                        float* __restrict__ out) {
    int tid = threadIdx.x;  // 640 threads
    int g = tid / NCLS, c = tid % NCLS;
    float s = 0.f;
#pragma unroll 8
    for (int h = 0; h < HID; h++) s += g_pool[g * HID + h] * Wc[h * NCLS + c];
    float cnt = (float)max(g_cnt[g], 1);
    out[tid] = s / cnt + bc[c];
}

// ---------------- launch ----------------
extern "C" void kernel_launch(void* const* d_in, const int* in_sizes, int n_in,
                              void* d_out, int out_size) {
    const float* x  = (const float*)d_in[0];
    const float* W1 = (const float*)d_in[1];
    const float* b1 = (const float*)d_in[2];
    const float* W2 = (const float*)d_in[3];
    const float* b2 = (const float*)d_in[4];
    const float* Wc = (const float*)d_in[5];
    const float* bc = (const float*)d_in[6];
    const void* ei    = d_in[7];
    const void* batch = d_in[8];
    float* out = (float*)d_out;

    const int GEMM128_SMEM = (128 * 128 + 16 * 128) * 4;  // 72 KB

    static float* p_aggx = nullptr;
    static float* p_h = nullptr;
    static float* p_t = nullptr;
    if (!p_aggx) {
        cudaGetSymbolAddress((void**)&p_aggx, g_aggx);
        cudaGetSymbolAddress((void**)&p_h, g_h);
        cudaGetSymbolAddress((void**)&p_t, g_t);
        cudaFuncSetAttribute(k_gemm128,
                             cudaFuncAttributeMaxDynamicSharedMemorySize,
                             GEMM128_SMEM);
    }

    // dtype detection + graph structure
    k_detect<<<1, 1>>>((const int*)ei);
    k_init_deg<<<(NN + 255) / 256, 256>>>();
    k_hist<<<(NE + 511) / 512, 512>>>(ei);
    k_scan_a<<<SCAN_BLK, 256>>>();
    k_scan_b<<<1, 128>>>();
    k_scan_c<<<(NN + 255) / 256, 256>>>();
    k_build<<<(NE + 511) / 512, 512>>>(ei);

    // layer 1: aggregate-then-transform   h = relu((A x) W1 + b1)
    k_agg1<<<(NN * 32 + 255) / 256, 256>>>(x);
    k_gemm64<<<888, 128>>>(p_aggx, W1, b1, p_h, NN);

    // layer 2: transform-then-aggregate   h = relu(A (h W2) + b2)
    k_gemm128<<<444, 128, GEMM128_SMEM>>>(p_h, W2, p_t, NN);
    k_agg2<<<(NN * 32 + 255) / 256, 256>>>(b2);

    // mean pool + classifier
    k_pool_init<<<(NG * HID + 255) / 256, 256>>>();
    k_pool_acc<<<POOL_BLOCKS, 128>>>(batch);
    k_final<<<1, NG * NCLS>>>(Wc, bc, out);
}